// round 14
// baseline (speedup 1.0000x reference)
#include <cuda_runtime.h>
#include <cuda_fp16.h>
#include <math.h>
#include <stdint.h>

// Problem constants
constexpr int Bv = 8;
constexpr int Tv = 2048;
constexpr int Dv = 512;
constexpr int Hv = 2048;
constexpr int BT = Bv * Tv;            // 16384
constexpr int TD = Tv * Dv;            // 1048576
constexpr int N2D = Bv * 2 * Dv;       // 8192
constexpr int NKVQ = 3 * Dv;           // 1536
constexpr int BTD = Bv * Tv * Dv;      // 8388608

// ---------------- scratch (device globals) ----------------
__device__ __half g_h   [BTD];                 // LN1 out
__device__ float  g_KVQ [(size_t)BT * NKVQ];   // K|V|Q fused, fp32
__device__ __half g_expw[(size_t)Tv * Tv];
__device__ __half g_U   [(size_t)Tv * N2D];    // interleaved (den,num) pairs
__device__ __half g_Y   [BTD];
__device__ float  g_out [BTD];
__device__ __half g_h2  [BTD];
__device__ __half g_a1  [(size_t)BT * Hv];
// half weight copies [K][N]
__device__ __half g_Wkvq[Dv * NKVQ];
__device__ float  g_bkvq[NKVQ];
__device__ __half g_Wo  [Dv * Dv];
__device__ __half g_W1  [Dv * Hv];
__device__ __half g_W2  [Hv * Dv];

// ---------------- fused weight prep ----------------
__global__ void prep_kernel(const float* __restrict__ Wk,
                            const float* __restrict__ Wv,
                            const float* __restrict__ Wq,
                            const float* __restrict__ Wo,
                            const float* __restrict__ W1,
                            const float* __restrict__ W2,
                            const float* __restrict__ bk,
                            const float* __restrict__ bv,
                            const float* __restrict__ bq,
                            __half* __restrict__ dWkvq,
                            __half* __restrict__ dWo,
                            __half* __restrict__ dW1,
                            __half* __restrict__ dW2,
                            float* __restrict__ dbkvq) {
    const int c = blockIdx.x * blockDim.x + threadIdx.x;
    if (c < 1536)
        dbkvq[c] = (c < 512) ? bk[c] : (c < 1024) ? bv[c - 512] : bq[c - 1024];

    float4 v;
    __half* dst;
    int dc;
    if (c < 196608) {
        int d  = c / 384;
        int jj = c - d * 384;
        int seg = jj >> 7;
        int off = jj & 127;
        const float* W = (seg == 0) ? Wk : (seg == 1) ? Wv : Wq;
        v = ((const float4*)(W + (size_t)d * 512))[off];
        dst = dWkvq; dc = c;
    } else if (c < 262144) {
        dc = c - 196608;
        v = ((const float4*)Wo)[dc];
        dst = dWo;
    } else if (c < 524288) {
        dc = c - 262144;
        v = ((const float4*)W1)[dc];
        dst = dW1;
    } else {
        dc = c - 524288;
        v = ((const float4*)W2)[dc];
        dst = dW2;
    }
    ((__half2*)dst)[dc * 2 + 0] = __floats2half2_rn(v.x, v.y);
    ((__half2*)dst)[dc * 2 + 1] = __floats2half2_rn(v.z, v.w);
}

// ---------------- LayerNorm: 128 thr/row, float4, half out ----------------
__global__ void ln_kernel(const float* __restrict__ x,
                          const float* __restrict__ g,
                          const float* __restrict__ b,
                          __half* __restrict__ y) {
    const int row = blockIdx.x;
    const int t = threadIdx.x;          // 0..127
    const float4* xr = (const float4*)(x + (size_t)row * Dv);
    float4 v = xr[t];
    float s  = v.x + v.y + v.z + v.w;
    float sq = v.x * v.x + v.y * v.y + v.z * v.z + v.w * v.w;
    #pragma unroll
    for (int off = 16; off > 0; off >>= 1) {
        s  += __shfl_down_sync(0xffffffffu, s,  off);
        sq += __shfl_down_sync(0xffffffffu, sq, off);
    }
    __shared__ float ssum[4], ssq[4];
    __shared__ float s_mu, s_rstd;
    const int wid = t >> 5, lane = t & 31;
    if (lane == 0) { ssum[wid] = s; ssq[wid] = sq; }
    __syncthreads();
    if (t == 0) {
        float ts = ssum[0] + ssum[1] + ssum[2] + ssum[3];
        float tq = ssq[0] + ssq[1] + ssq[2] + ssq[3];
        float mu  = ts * (1.0f / Dv);
        float var = tq * (1.0f / Dv) - mu * mu;
        s_mu = mu;
        s_rstd = rsqrtf(var + 1e-5f);
    }
    __syncthreads();
    const float mu = s_mu, rstd = s_rstd;
    float4 gg = ((const float4*)g)[t];
    float4 bb = ((const float4*)b)[t];
    float o0 = (v.x - mu) * rstd * gg.x + bb.x;
    float o1 = (v.y - mu) * rstd * gg.y + bb.y;
    float o2 = (v.z - mu) * rstd * gg.z + bb.z;
    float o3 = (v.w - mu) * rstd * gg.w + bb.w;
    __half2* yr = (__half2*)(y + (size_t)row * Dv);
    yr[t * 2 + 0] = __floats2half2_rn(o0, o1);
    yr[t * 2 + 1] = __floats2half2_rn(o2, o3);
}

// ---------------- exp_w: float4 vectorized, half out ----------------
__global__ void expw_kernel(const float* __restrict__ w, __half* __restrict__ ew) {
    const int row = blockIdx.x;
    const int t = threadIdx.x;          // 0..255
    const float4* wr = (const float4*)(w + (size_t)row * Tv);
    float4 a = wr[t * 2], c = wr[t * 2 + 1];
    float m = fmaxf(fmaxf(fmaxf(a.x, a.y), fmaxf(a.z, a.w)),
                    fmaxf(fmaxf(c.x, c.y), fmaxf(c.z, c.w)));
    #pragma unroll
    for (int off = 16; off > 0; off >>= 1)
        m = fmaxf(m, __shfl_down_sync(0xffffffffu, m, off));
    __shared__ float sm[8];
    __shared__ float s_max;
    const int wid = t >> 5, lane = t & 31;
    if (lane == 0) sm[wid] = m;
    __syncthreads();
    if (t == 0) {
        float mm = sm[0];
        #pragma unroll
        for (int i = 1; i < 8; i++) mm = fmaxf(mm, sm[i]);
        s_max = mm;
    }
    __syncthreads();
    const float mx = s_max;
    __half2* er = (__half2*)(ew + (size_t)row * Tv);
    er[t * 4 + 0] = __floats2half2_rn(expf(a.x - mx), expf(a.y - mx));
    er[t * 4 + 1] = __floats2half2_rn(expf(a.z - mx), expf(a.w - mx));
    er[t * 4 + 2] = __floats2half2_rn(expf(c.x - mx), expf(c.y - mx));
    er[t * 4 + 3] = __floats2half2_rn(expf(c.z - mx), expf(c.w - mx));
}

// ---------------- fused kmax + build U (vectorized: 4 d per thread) --------
__global__ void buildU_kernel(const float* __restrict__ KVQ,
                              __half* __restrict__ U) {
    const int idx = blockIdx.x * blockDim.x + threadIdx.x;
    if (idx >= TD / 4) return;
    const int t  = idx >> 7;            // 128 d-groups per t
    const int d4 = (idx & 127) << 2;    // d base (multiple of 4)
    float4 kv[Bv];
    float4 m4 = make_float4(-1e30f, -1e30f, -1e30f, -1e30f);
    #pragma unroll
    for (int b = 0; b < Bv; b++) {
        kv[b] = *(const float4*)&KVQ[((size_t)(b * Tv + t)) * NKVQ + d4];
        m4.x = fmaxf(m4.x, kv[b].x);
        m4.y = fmaxf(m4.y, kv[b].y);
        m4.z = fmaxf(m4.z, kv[b].z);
        m4.w = fmaxf(m4.w, kv[b].w);
    }
    __half2* Ubase = (__half2*)U + (size_t)t * (N2D / 2) + d4;
    #pragma unroll
    for (int b = 0; b < Bv; b++) {
        float4 vv = *(const float4*)&KVQ[((size_t)(b * Tv + t)) * NKVQ + 512 + d4];
        float e0 = expf(kv[b].x - m4.x);
        float e1 = expf(kv[b].y - m4.y);
        float e2 = expf(kv[b].z - m4.z);
        float e3 = expf(kv[b].w - m4.w);
        __align__(16) __half2 hh[4];
        hh[0] = __floats2half2_rn(e0, e0 * vv.x);
        hh[1] = __floats2half2_rn(e1, e1 * vv.y);
        hh[2] = __floats2half2_rn(e2, e2 * vv.z);
        hh[3] = __floats2half2_rn(e3, e3 * vv.w);
        *(uint4*)(Ubase + b * 512) = *(uint4*)hh;
    }
}

// ============================================================================
// FP16 mma.sync GEMM: 64x64x64 CTA tile, 4 warps (32x32 warp tiles),
// 3-stage cp.async (16KB/stage), fragment double-buffering, 4 CTAs/SM.
// ============================================================================
__device__ __forceinline__ float gelu_exact(float v) {
    return 0.5f * v * (1.0f + erff(v * 0.70710678118654752f));
}
__device__ __forceinline__ void cp_async16h(__half* dst, const __half* src) {
    uint32_t d = (uint32_t)__cvta_generic_to_shared(dst);
    asm volatile("cp.async.cg.shared.global [%0], [%1], 16;\n" :: "r"(d), "l"(src));
}
__device__ __forceinline__ void ldsm4(uint32_t* r, uint32_t addr) {
    asm volatile("ldmatrix.sync.aligned.m8n8.x4.shared.b16 {%0,%1,%2,%3}, [%4];"
        : "=r"(r[0]), "=r"(r[1]), "=r"(r[2]), "=r"(r[3]) : "r"(addr));
}
__device__ __forceinline__ void ldsm4t(uint32_t* r, uint32_t addr) {
    asm volatile("ldmatrix.sync.aligned.m8n8.x4.trans.shared.b16 {%0,%1,%2,%3}, [%4];"
        : "=r"(r[0]), "=r"(r[1]), "=r"(r[2]), "=r"(r[3]) : "r"(addr));
}
__device__ __forceinline__ void mma_f16(float* c, const uint32_t* a, const uint32_t* b) {
    asm volatile(
        "mma.sync.aligned.m16n8k16.row.col.f32.f16.f16.f32 "
        "{%0,%1,%2,%3}, {%4,%5,%6,%7}, {%8,%9}, {%0,%1,%2,%3};\n"
        : "+f"(c[0]), "+f"(c[1]), "+f"(c[2]), "+f"(c[3])
        : "r"(a[0]), "r"(a[1]), "r"(a[2]), "r"(a[3]), "r"(b[0]), "r"(b[1]));
}

constexpr int GM = 64;                         // CTA M tile
constexpr int GN = 64;                         // CTA N tile
constexpr int BK = 64;
constexpr int A_HALVES = GM * BK;              // 4096 halves, 8KB
constexpr int B_HALVES = BK * GN;              // 4096 halves, 8KB
constexpr int STAGE_HALVES = A_HALVES + B_HALVES;     // 8192
constexpr int SMEM_BYTES = 3 * STAGE_HALVES * 2;      // 49152

// EPI: 1=+bias(f32), 2=+bias+res(f32), 3=gelu(+bias)->half,
//      4=gelu(+bias)+res(f32), 5=AFT gate (den,num)->sigmoid(Q)*num/den ->half
template <int EPI>
__global__ __launch_bounds__(128, 4)
void hgemm_kernel(const __half* __restrict__ A, const __half* __restrict__ B,
                  const float* __restrict__ bias, const float* __restrict__ res,
                  void* __restrict__ Cout, int M, int N, int K) {
    extern __shared__ __half sm[];
    const int tid  = threadIdx.x;
    const int lane = tid & 31;
    const int warp = tid >> 5;
    const int wrow = warp & 1;     // 2 x 32 rows
    const int wcol = warp >> 1;    // 2 x 32 cols
    const int bM = blockIdx.y * GM;
    const int bN = blockIdx.x * GN;
    const int lane15 = lane & 15;
    const int lanehi = lane >> 4;

    float c[2][4][4];
    #pragma unroll
    for (int i = 0; i < 2; i++)
        #pragma unroll
        for (int j = 0; j < 4; j++)
            #pragma unroll
            for (int k = 0; k < 4; k++) c[i][j][k] = 0.f;

    const int nk = K / BK;

    auto load_stage = [&](int kt, int s) {
        __half* As = sm + s * STAGE_HALVES;
        __half* Bs = As + A_HALVES;
        const __half* Ag = A + (size_t)bM * K + kt * BK;
        const __half* Bg = B + (size_t)(kt * BK) * N + bN;
        #pragma unroll
        for (int i = 0; i < 4; i++) {            // A: 512 16B chunks
            int ch = i * 128 + tid;
            int r = ch >> 3, cc = ch & 7;
            int pc = cc ^ (r & 7);
            cp_async16h(As + r * 64 + pc * 8, Ag + (size_t)r * K + cc * 8);
        }
        #pragma unroll
        for (int i = 0; i < 4; i++) {            // B: 512 16B chunks (64 rows x 8)
            int ch = i * 128 + tid;
            int k = ch >> 3, cc = ch & 7;
            int pc = cc ^ (k & 7);
            cp_async16h(Bs + k * 64 + pc * 8, Bg + (size_t)k * N + cc * 8);
        }
        asm volatile("cp.async.commit_group;\n");
    };

    load_stage(0, 0);
    load_stage(1, 1);

    int s_cur = 0;
    int s_next = 2;

    for (int kt = 0; kt < nk; kt++) {
        asm volatile("cp.async.wait_group 1;\n");
        __syncthreads();

        if (kt + 2 < nk) load_stage(kt + 2, s_next);
        else asm volatile("cp.async.commit_group;\n");

        const __half* As = sm + s_cur * STAGE_HALVES;
        uint32_t a_base = (uint32_t)__cvta_generic_to_shared(As);
        uint32_t b_base = a_base + A_HALVES * 2;
        if (++s_cur == 3) s_cur = 0;
        if (++s_next == 3) s_next = 0;

        uint32_t a[2][2][4], b[2][2][4];

        auto load_a = [&](int k16, uint32_t (*af)[4]) {
            #pragma unroll
            for (int mt = 0; mt < 2; mt++) {
                int r = wrow * 32 + mt * 16 + lane15;
                int cc = 2 * k16 + lanehi;
                int pc = cc ^ (r & 7);
                ldsm4(af[mt], a_base + (r * 64 + pc * 8) * 2);
            }
        };
        auto load_b = [&](int k16, uint32_t (*bf)[4]) {
            #pragma unroll
            for (int nt2 = 0; nt2 < 2; nt2++) {
                int kr = k16 * 16 + lane15;
                int cc = wcol * 4 + nt2 * 2 + lanehi;
                int pc = cc ^ (kr & 7);
                ldsm4t(bf[nt2], b_base + (kr * 64 + pc * 8) * 2);
            }
        };

        load_a(0, a[0]);
        load_b(0, b[0]);

        #pragma unroll
        for (int k16 = 0; k16 < 4; k16++) {
            const int cur = k16 & 1;
            if (k16 < 3) {
                load_a(k16 + 1, a[cur ^ 1]);
                load_b(k16 + 1, b[cur ^ 1]);
            }
            #pragma unroll
            for (int mt = 0; mt < 2; mt++)
                #pragma unroll
                for (int nt = 0; nt < 4; nt++)
                    mma_f16(c[mt][nt], a[cur][mt], &b[cur][nt >> 1][(nt & 1) * 2]);
        }
    }

    // epilogue
    #pragma unroll
    for (int mt = 0; mt < 2; mt++) {
        #pragma unroll
        for (int nt = 0; nt < 4; nt++) {
            const int row0 = bM + wrow * 32 + mt * 16 + (lane >> 2);
            const int col  = bN + wcol * 32 + nt * 8 + (lane & 3) * 2;
            #pragma unroll
            for (int h = 0; h < 2; h++) {
                const size_t row = row0 + h * 8;
                float v0 = c[mt][nt][h * 2 + 0];
                float v1 = c[mt][nt][h * 2 + 1];
                if (EPI == 5) {
                    int b  = col >> 10;
                    int d  = (col & 1023) >> 1;
                    size_t rb = (size_t)b * Tv + row;
                    float q = res[rb * NKVQ + 1024 + d];   // res = KVQ base
                    float sig = 1.0f / (1.0f + expf(-q));
                    ((__half*)Cout)[rb * 512 + d] = __float2half_rn(sig * v1 / v0);
                    continue;
                }
                if (EPI >= 1) { v0 += bias[col]; v1 += bias[col + 1]; }
                if (EPI == 3 || EPI == 4) { v0 = gelu_exact(v0); v1 = gelu_exact(v1); }
                if (EPI == 2 || EPI == 4) {
                    v0 += res[row * N + col];
                    v1 += res[row * N + col + 1];
                }
                if (EPI == 3) {
                    *(__half2*)((__half*)Cout + row * N + col) =
                        __floats2half2_rn(v0, v1);
                } else {
                    *(float2*)((float*)Cout + row * N + col) = make_float2(v0, v1);
                }
            }
        }
    }
}

// ---------------- launch ----------------
extern "C" void kernel_launch(void* const* d_in, const int* in_sizes, int n_in,
                              void* d_out, int out_size) {
    const float* x     = (const float*)d_in[0];
    const float* ln1_g = (const float*)d_in[1];
    const float* ln1_b = (const float*)d_in[2];
    const float* Wk    = (const float*)d_in[3];
    const float* bk    = (const float*)d_in[4];
    const float* Wv    = (const float*)d_in[5];
    const float* bv    = (const float*)d_in[6];
    const float* Wq    = (const float*)d_in[7];
    const float* bq    = (const float*)d_in[8];
    const float* w     = (const float*)d_in[9];
    const float* Wo    = (const float*)d_in[10];
    const float* bo    = (const float*)d_in[11];
    const float* ln2_g = (const float*)d_in[12];
    const float* ln2_b = (const float*)d_in[13];
    const float* W1    = (const float*)d_in[14];
    const float* b1    = (const float*)d_in[15];
    const float* W2    = (const float*)d_in[16];
    const float* b2    = (const float*)d_in[17];
    float* out = (float*)d_out;

    __half *p_h, *p_expw, *p_U, *p_Y, *p_h2, *p_a1, *p_Wkvq, *p_Wo, *p_W1, *p_W2;
    float *p_KVQ, *p_out, *p_bkvq;
    cudaGetSymbolAddress((void**)&p_h,    g_h);
    cudaGetSymbolAddress((void**)&p_KVQ,  g_KVQ);
    cudaGetSymbolAddress((void**)&p_expw, g_expw);
    cudaGetSymbolAddress((void**)&p_U,    g_U);
    cudaGetSymbolAddress((void**)&p_Y,    g_Y);
    cudaGetSymbolAddress((void**)&p_out,  g_out);
    cudaGetSymbolAddress((void**)&p_h2,   g_h2);
    cudaGetSymbolAddress((void**)&p_a1,   g_a1);
    cudaGetSymbolAddress((void**)&p_Wkvq, g_Wkvq);
    cudaGetSymbolAddress((void**)&p_bkvq, g_bkvq);
    cudaGetSymbolAddress((void**)&p_Wo,   g_Wo);
    cudaGetSymbolAddress((void**)&p_W1,   g_W1);
    cudaGetSymbolAddress((void**)&p_W2,   g_W2);

    cudaFuncSetAttribute(hgemm_kernel<1>, cudaFuncAttributeMaxDynamicSharedMemorySize, SMEM_BYTES);
    cudaFuncSetAttribute(hgemm_kernel<2>, cudaFuncAttributeMaxDynamicSharedMemorySize, SMEM_BYTES);
    cudaFuncSetAttribute(hgemm_kernel<3>, cudaFuncAttributeMaxDynamicSharedMemorySize, SMEM_BYTES);
    cudaFuncSetAttribute(hgemm_kernel<4>, cudaFuncAttributeMaxDynamicSharedMemorySize, SMEM_BYTES);
    cudaFuncSetAttribute(hgemm_kernel<5>, cudaFuncAttributeMaxDynamicSharedMemorySize, SMEM_BYTES);

    // 0. fused weight prep
    prep_kernel<<<3072, 256>>>(Wk, Wv, Wq, Wo, W1, W2, bk, bv, bq,
                               p_Wkvq, p_Wo, p_W1, p_W2, p_bkvq);

    // 1. exp_w (independent)
    expw_kernel<<<Tv, 256>>>(w, p_expw);

    // 2. LN1
    ln_kernel<<<BT, 128>>>(x, ln1_g, ln1_b, p_h);

    // 3. fused KVQ projection: [16384,512] @ [512,1536]
    {
        dim3 grid(NKVQ / GN, BT / GM);
        hgemm_kernel<1><<<grid, 128, SMEM_BYTES>>>(p_h, p_Wkvq, p_bkvq, nullptr,
                                                   p_KVQ, BT, NKVQ, Dv);
    }

    // 4. fused kmax + build U (vectorized)
    buildU_kernel<<<TD / 4 / 256, 256>>>(p_KVQ, p_U);

    // 5. AFT core GEMM + fused gate: Y = sigmoid(Q) * num/den (half out)
    {
        dim3 grid(N2D / GN, Tv / GM);
        hgemm_kernel<5><<<grid, 128, SMEM_BYTES>>>(p_expw, p_U, nullptr, p_KVQ,
                                                   p_Y, Tv, N2D, Tv);
    }

    // 6. out = Y @ Wo + bo + x
    {
        dim3 grid(Dv / GN, BT / GM);
        hgemm_kernel<2><<<grid, 128, SMEM_BYTES>>>(p_Y, p_Wo, bo, x,
                                                   p_out, BT, Dv, Dv);
    }

    // 7. LN2
    ln_kernel<<<BT, 128>>>(p_out, ln2_g, ln2_b, p_h2);

    // 8. a1 = gelu(h2 @ W1 + b1) -> half
    {
        dim3 grid(Hv / GN, BT / GM);
        hgemm_kernel<3><<<grid, 128, SMEM_BYTES>>>(p_h2, p_W1, b1, nullptr,
                                                   p_a1, BT, Hv, Dv);
    }

    // 9. out = gelu(a1 @ W2 + b2) + out_residual
    {
        dim3 grid(Dv / GN, BT / GM);
        hgemm_kernel<4><<<grid, 128, SMEM_BYTES>>>(p_a1, p_W2, b2, p_out,
                                                   out, BT, Dv, Hv);
    }
}

// round 15
// speedup vs baseline: 1.0182x; 1.0182x over previous
#include <cuda_runtime.h>
#include <cuda_fp16.h>
#include <math.h>
#include <stdint.h>

// Problem constants
constexpr int Bv = 8;
constexpr int Tv = 2048;
constexpr int Dv = 512;
constexpr int Hv = 2048;
constexpr int BT = Bv * Tv;            // 16384
constexpr int TD = Tv * Dv;            // 1048576
constexpr int N2D = Bv * 2 * Dv;       // 8192
constexpr int NKVQ = 3 * Dv;           // 1536
constexpr int BTD = Bv * Tv * Dv;      // 8388608

// ---------------- scratch (device globals) ----------------
__device__ __half g_h   [BTD];                 // LN1 out
__device__ __half g_KVQ [(size_t)BT * NKVQ];   // K|V|Q fused, fp16
__device__ __half g_expw[(size_t)Tv * Tv];
__device__ __half g_U   [(size_t)Tv * N2D];    // interleaved (den,num) pairs
__device__ __half g_Y   [BTD];
__device__ float  g_out [BTD];
__device__ __half g_h2  [BTD];
__device__ __half g_a1  [(size_t)BT * Hv];
// half weight copies [K][N]
__device__ __half g_Wkvq[Dv * NKVQ];
__device__ float  g_bkvq[NKVQ];
__device__ __half g_Wo  [Dv * Dv];
__device__ __half g_W1  [Dv * Hv];
__device__ __half g_W2  [Hv * Dv];

// ---------------- fused weight prep ----------------
__global__ void prep_kernel(const float* __restrict__ Wk,
                            const float* __restrict__ Wv,
                            const float* __restrict__ Wq,
                            const float* __restrict__ Wo,
                            const float* __restrict__ W1,
                            const float* __restrict__ W2,
                            const float* __restrict__ bk,
                            const float* __restrict__ bv,
                            const float* __restrict__ bq,
                            __half* __restrict__ dWkvq,
                            __half* __restrict__ dWo,
                            __half* __restrict__ dW1,
                            __half* __restrict__ dW2,
                            float* __restrict__ dbkvq) {
    const int c = blockIdx.x * blockDim.x + threadIdx.x;
    if (c < 1536)
        dbkvq[c] = (c < 512) ? bk[c] : (c < 1024) ? bv[c - 512] : bq[c - 1024];

    float4 v;
    __half* dst;
    int dc;
    if (c < 196608) {
        int d  = c / 384;
        int jj = c - d * 384;
        int seg = jj >> 7;
        int off = jj & 127;
        const float* W = (seg == 0) ? Wk : (seg == 1) ? Wv : Wq;
        v = ((const float4*)(W + (size_t)d * 512))[off];
        dst = dWkvq; dc = c;
    } else if (c < 262144) {
        dc = c - 196608;
        v = ((const float4*)Wo)[dc];
        dst = dWo;
    } else if (c < 524288) {
        dc = c - 262144;
        v = ((const float4*)W1)[dc];
        dst = dW1;
    } else {
        dc = c - 524288;
        v = ((const float4*)W2)[dc];
        dst = dW2;
    }
    ((__half2*)dst)[dc * 2 + 0] = __floats2half2_rn(v.x, v.y);
    ((__half2*)dst)[dc * 2 + 1] = __floats2half2_rn(v.z, v.w);
}

// ---------------- LayerNorm: 128 thr/row, float4, half out ----------------
__global__ void ln_kernel(const float* __restrict__ x,
                          const float* __restrict__ g,
                          const float* __restrict__ b,
                          __half* __restrict__ y) {
    const int row = blockIdx.x;
    const int t = threadIdx.x;          // 0..127
    const float4* xr = (const float4*)(x + (size_t)row * Dv);
    float4 v = xr[t];
    float s  = v.x + v.y + v.z + v.w;
    float sq = v.x * v.x + v.y * v.y + v.z * v.z + v.w * v.w;
    #pragma unroll
    for (int off = 16; off > 0; off >>= 1) {
        s  += __shfl_down_sync(0xffffffffu, s,  off);
        sq += __shfl_down_sync(0xffffffffu, sq, off);
    }
    __shared__ float ssum[4], ssq[4];
    __shared__ float s_mu, s_rstd;
    const int wid = t >> 5, lane = t & 31;
    if (lane == 0) { ssum[wid] = s; ssq[wid] = sq; }
    __syncthreads();
    if (t == 0) {
        float ts = ssum[0] + ssum[1] + ssum[2] + ssum[3];
        float tq = ssq[0] + ssq[1] + ssq[2] + ssq[3];
        float mu  = ts * (1.0f / Dv);
        float var = tq * (1.0f / Dv) - mu * mu;
        s_mu = mu;
        s_rstd = rsqrtf(var + 1e-5f);
    }
    __syncthreads();
    const float mu = s_mu, rstd = s_rstd;
    float4 gg = ((const float4*)g)[t];
    float4 bb = ((const float4*)b)[t];
    float o0 = (v.x - mu) * rstd * gg.x + bb.x;
    float o1 = (v.y - mu) * rstd * gg.y + bb.y;
    float o2 = (v.z - mu) * rstd * gg.z + bb.z;
    float o3 = (v.w - mu) * rstd * gg.w + bb.w;
    __half2* yr = (__half2*)(y + (size_t)row * Dv);
    yr[t * 2 + 0] = __floats2half2_rn(o0, o1);
    yr[t * 2 + 1] = __floats2half2_rn(o2, o3);
}

// ---------------- exp_w: float4 vectorized, half out ----------------
__global__ void expw_kernel(const float* __restrict__ w, __half* __restrict__ ew) {
    const int row = blockIdx.x;
    const int t = threadIdx.x;          // 0..255
    const float4* wr = (const float4*)(w + (size_t)row * Tv);
    float4 a = wr[t * 2], c = wr[t * 2 + 1];
    float m = fmaxf(fmaxf(fmaxf(a.x, a.y), fmaxf(a.z, a.w)),
                    fmaxf(fmaxf(c.x, c.y), fmaxf(c.z, c.w)));
    #pragma unroll
    for (int off = 16; off > 0; off >>= 1)
        m = fmaxf(m, __shfl_down_sync(0xffffffffu, m, off));
    __shared__ float sm[8];
    __shared__ float s_max;
    const int wid = t >> 5, lane = t & 31;
    if (lane == 0) sm[wid] = m;
    __syncthreads();
    if (t == 0) {
        float mm = sm[0];
        #pragma unroll
        for (int i = 1; i < 8; i++) mm = fmaxf(mm, sm[i]);
        s_max = mm;
    }
    __syncthreads();
    const float mx = s_max;
    __half2* er = (__half2*)(ew + (size_t)row * Tv);
    er[t * 4 + 0] = __floats2half2_rn(expf(a.x - mx), expf(a.y - mx));
    er[t * 4 + 1] = __floats2half2_rn(expf(a.z - mx), expf(a.w - mx));
    er[t * 4 + 2] = __floats2half2_rn(expf(c.x - mx), expf(c.y - mx));
    er[t * 4 + 3] = __floats2half2_rn(expf(c.z - mx), expf(c.w - mx));
}

// ---------------- fused kmax + build U (half KVQ, 4 d per thread) ----------
__global__ void buildU_kernel(const __half* __restrict__ KVQ,
                              __half* __restrict__ U) {
    const int idx = blockIdx.x * blockDim.x + threadIdx.x;
    if (idx >= TD / 4) return;
    const int t  = idx >> 7;            // 128 d-groups per t
    const int d4 = (idx & 127) << 2;    // d base (multiple of 4)
    float4 kv[Bv];
    float4 m4 = make_float4(-1e30f, -1e30f, -1e30f, -1e30f);
    #pragma unroll
    for (int b = 0; b < Bv; b++) {
        uint2 raw = *(const uint2*)&KVQ[((size_t)(b * Tv + t)) * NKVQ + d4];
        float2 f01 = __half22float2(*(__half2*)&raw.x);
        float2 f23 = __half22float2(*(__half2*)&raw.y);
        kv[b] = make_float4(f01.x, f01.y, f23.x, f23.y);
        m4.x = fmaxf(m4.x, kv[b].x);
        m4.y = fmaxf(m4.y, kv[b].y);
        m4.z = fmaxf(m4.z, kv[b].z);
        m4.w = fmaxf(m4.w, kv[b].w);
    }
    __half2* Ubase = (__half2*)U + (size_t)t * (N2D / 2) + d4;
    #pragma unroll
    for (int b = 0; b < Bv; b++) {
        uint2 rawv = *(const uint2*)&KVQ[((size_t)(b * Tv + t)) * NKVQ + 512 + d4];
        float2 v01 = __half22float2(*(__half2*)&rawv.x);
        float2 v23 = __half22float2(*(__half2*)&rawv.y);
        float e0 = expf(kv[b].x - m4.x);
        float e1 = expf(kv[b].y - m4.y);
        float e2 = expf(kv[b].z - m4.z);
        float e3 = expf(kv[b].w - m4.w);
        __align__(16) __half2 hh[4];
        hh[0] = __floats2half2_rn(e0, e0 * v01.x);
        hh[1] = __floats2half2_rn(e1, e1 * v01.y);
        hh[2] = __floats2half2_rn(e2, e2 * v23.x);
        hh[3] = __floats2half2_rn(e3, e3 * v23.y);
        *(uint4*)(Ubase + b * 512) = *(uint4*)hh;
    }
}

// ============================================================================
// FP16 mma.sync GEMM (R13-proven optimum): 64x128x64 CTA tile, 4 warps
// (32x64 warp tiles), 3-stage cp.async, fragment double-buffering, 3 CTAs/SM.
// ============================================================================
__device__ __forceinline__ float gelu_exact(float v) {
    return 0.5f * v * (1.0f + erff(v * 0.70710678118654752f));
}
__device__ __forceinline__ void cp_async16h(__half* dst, const __half* src) {
    uint32_t d = (uint32_t)__cvta_generic_to_shared(dst);
    asm volatile("cp.async.cg.shared.global [%0], [%1], 16;\n" :: "r"(d), "l"(src));
}
__device__ __forceinline__ void ldsm4(uint32_t* r, uint32_t addr) {
    asm volatile("ldmatrix.sync.aligned.m8n8.x4.shared.b16 {%0,%1,%2,%3}, [%4];"
        : "=r"(r[0]), "=r"(r[1]), "=r"(r[2]), "=r"(r[3]) : "r"(addr));
}
__device__ __forceinline__ void ldsm4t(uint32_t* r, uint32_t addr) {
    asm volatile("ldmatrix.sync.aligned.m8n8.x4.trans.shared.b16 {%0,%1,%2,%3}, [%4];"
        : "=r"(r[0]), "=r"(r[1]), "=r"(r[2]), "=r"(r[3]) : "r"(addr));
}
__device__ __forceinline__ void mma_f16(float* c, const uint32_t* a, const uint32_t* b) {
    asm volatile(
        "mma.sync.aligned.m16n8k16.row.col.f32.f16.f16.f32 "
        "{%0,%1,%2,%3}, {%4,%5,%6,%7}, {%8,%9}, {%0,%1,%2,%3};\n"
        : "+f"(c[0]), "+f"(c[1]), "+f"(c[2]), "+f"(c[3])
        : "r"(a[0]), "r"(a[1]), "r"(a[2]), "r"(a[3]), "r"(b[0]), "r"(b[1]));
}

constexpr int GM = 64;                         // CTA M tile
constexpr int BK = 64;
constexpr int A_HALVES = GM * BK;              // 4096 halves, 8KB
constexpr int B_HALVES = BK * 128;             // 8192 halves, 16KB
constexpr int STAGE_HALVES = A_HALVES + B_HALVES;     // 12288
constexpr int SMEM_BYTES = 3 * STAGE_HALVES * 2;      // 73728

// EPI: 1=+bias->half (KVQ), 2=+bias+res(f32)->f32, 3=gelu(+bias)->half,
//      4=gelu(+bias)+res(f32)->f32, 5=AFT gate (den,num)->sigmoid(Q)*num/den ->half
template <int EPI>
__global__ __launch_bounds__(128, 3)
void hgemm_kernel(const __half* __restrict__ A, const __half* __restrict__ B,
                  const float* __restrict__ bias, const void* __restrict__ res,
                  void* __restrict__ Cout, int M, int N, int K) {
    extern __shared__ __half sm[];
    const int tid  = threadIdx.x;
    const int lane = tid & 31;
    const int warp = tid >> 5;
    const int wrow = warp & 1;     // 2 x 32 rows
    const int wcol = warp >> 1;    // 2 x 64 cols
    const int bM = blockIdx.y * GM;
    const int bN = blockIdx.x * 128;
    const int lane15 = lane & 15;
    const int lanehi = lane >> 4;

    float c[2][8][4];
    #pragma unroll
    for (int i = 0; i < 2; i++)
        #pragma unroll
        for (int j = 0; j < 8; j++)
            #pragma unroll
            for (int k = 0; k < 4; k++) c[i][j][k] = 0.f;

    const int nk = K / BK;

    auto load_stage = [&](int kt, int s) {
        __half* As = sm + s * STAGE_HALVES;
        __half* Bs = As + A_HALVES;
        const __half* Ag = A + (size_t)bM * K + kt * BK;
        const __half* Bg = B + (size_t)(kt * BK) * N + bN;
        #pragma unroll
        for (int i = 0; i < 4; i++) {            // A: 512 16B chunks
            int ch = i * 128 + tid;
            int r = ch >> 3, cc = ch & 7;
            int pc = cc ^ (r & 7);
            cp_async16h(As + r * 64 + pc * 8, Ag + (size_t)r * K + cc * 8);
        }
        #pragma unroll
        for (int i = 0; i < 8; i++) {            // B: 1024 16B chunks
            int ch = i * 128 + tid;
            int k = ch >> 4, cc = ch & 15;
            int pc = cc ^ (k & 7);
            cp_async16h(Bs + k * 128 + pc * 8, Bg + (size_t)k * N + cc * 8);
        }
        asm volatile("cp.async.commit_group;\n");
    };

    load_stage(0, 0);
    load_stage(1, 1);

    int s_cur = 0;
    int s_next = 2;

    for (int kt = 0; kt < nk; kt++) {
        asm volatile("cp.async.wait_group 1;\n");
        __syncthreads();

        if (kt + 2 < nk) load_stage(kt + 2, s_next);
        else asm volatile("cp.async.commit_group;\n");

        const __half* As = sm + s_cur * STAGE_HALVES;
        uint32_t a_base = (uint32_t)__cvta_generic_to_shared(As);
        uint32_t b_base = a_base + A_HALVES * 2;
        if (++s_cur == 3) s_cur = 0;
        if (++s_next == 3) s_next = 0;

        uint32_t a[2][2][4], b[2][4][4];

        auto load_a = [&](int k16, uint32_t (*af)[4]) {
            #pragma unroll
            for (int mt = 0; mt < 2; mt++) {
                int r = wrow * 32 + mt * 16 + lane15;
                int cc = 2 * k16 + lanehi;
                int pc = cc ^ (r & 7);
                ldsm4(af[mt], a_base + (r * 64 + pc * 8) * 2);
            }
        };
        auto load_b = [&](int k16, uint32_t (*bf)[4]) {
            #pragma unroll
            for (int nt2 = 0; nt2 < 4; nt2++) {
                int kr = k16 * 16 + lane15;
                int cc = wcol * 8 + nt2 * 2 + lanehi;
                int pc = cc ^ (kr & 7);
                ldsm4t(bf[nt2], b_base + (kr * 128 + pc * 8) * 2);
            }
        };

        load_a(0, a[0]);
        load_b(0, b[0]);

        #pragma unroll
        for (int k16 = 0; k16 < 4; k16++) {
            const int cur = k16 & 1;
            if (k16 < 3) {
                load_a(k16 + 1, a[cur ^ 1]);
                load_b(k16 + 1, b[cur ^ 1]);
            }
            #pragma unroll
            for (int mt = 0; mt < 2; mt++)
                #pragma unroll
                for (int nt = 0; nt < 8; nt++)
                    mma_f16(c[mt][nt], a[cur][mt], &b[cur][nt >> 1][(nt & 1) * 2]);
        }
    }

    // epilogue
    #pragma unroll
    for (int mt = 0; mt < 2; mt++) {
        #pragma unroll
        for (int nt = 0; nt < 8; nt++) {
            const int row0 = bM + wrow * 32 + mt * 16 + (lane >> 2);
            const int col  = bN + wcol * 64 + nt * 8 + (lane & 3) * 2;
            #pragma unroll
            for (int h = 0; h < 2; h++) {
                const size_t row = row0 + h * 8;
                float v0 = c[mt][nt][h * 2 + 0];
                float v1 = c[mt][nt][h * 2 + 1];
                if (EPI == 5) {
                    int b  = col >> 10;
                    int d  = (col & 1023) >> 1;
                    size_t rb = (size_t)b * Tv + row;
                    float q = __half2float(
                        ((const __half*)res)[rb * NKVQ + 1024 + d]);  // res = KVQ
                    float sig = 1.0f / (1.0f + expf(-q));
                    ((__half*)Cout)[rb * 512 + d] = __float2half_rn(sig * v1 / v0);
                    continue;
                }
                if (EPI >= 1) { v0 += bias[col]; v1 += bias[col + 1]; }
                if (EPI == 3 || EPI == 4) { v0 = gelu_exact(v0); v1 = gelu_exact(v1); }
                if (EPI == 2 || EPI == 4) {
                    v0 += ((const float*)res)[row * N + col];
                    v1 += ((const float*)res)[row * N + col + 1];
                }
                if (EPI == 1 || EPI == 3) {
                    *(__half2*)((__half*)Cout + row * N + col) =
                        __floats2half2_rn(v0, v1);
                } else {
                    *(float2*)((float*)Cout + row * N + col) = make_float2(v0, v1);
                }
            }
        }
    }
}

// ---------------- launch ----------------
extern "C" void kernel_launch(void* const* d_in, const int* in_sizes, int n_in,
                              void* d_out, int out_size) {
    const float* x     = (const float*)d_in[0];
    const float* ln1_g = (const float*)d_in[1];
    const float* ln1_b = (const float*)d_in[2];
    const float* Wk    = (const float*)d_in[3];
    const float* bk    = (const float*)d_in[4];
    const float* Wv    = (const float*)d_in[5];
    const float* bv    = (const float*)d_in[6];
    const float* Wq    = (const float*)d_in[7];
    const float* bq    = (const float*)d_in[8];
    const float* w     = (const float*)d_in[9];
    const float* Wo    = (const float*)d_in[10];
    const float* bo    = (const float*)d_in[11];
    const float* ln2_g = (const float*)d_in[12];
    const float* ln2_b = (const float*)d_in[13];
    const float* W1    = (const float*)d_in[14];
    const float* b1    = (const float*)d_in[15];
    const float* W2    = (const float*)d_in[16];
    const float* b2    = (const float*)d_in[17];
    float* out = (float*)d_out;

    __half *p_h, *p_KVQ, *p_expw, *p_U, *p_Y, *p_h2, *p_a1, *p_Wkvq, *p_Wo,
           *p_W1, *p_W2;
    float *p_out, *p_bkvq;
    cudaGetSymbolAddress((void**)&p_h,    g_h);
    cudaGetSymbolAddress((void**)&p_KVQ,  g_KVQ);
    cudaGetSymbolAddress((void**)&p_expw, g_expw);
    cudaGetSymbolAddress((void**)&p_U,    g_U);
    cudaGetSymbolAddress((void**)&p_Y,    g_Y);
    cudaGetSymbolAddress((void**)&p_out,  g_out);
    cudaGetSymbolAddress((void**)&p_h2,   g_h2);
    cudaGetSymbolAddress((void**)&p_a1,   g_a1);
    cudaGetSymbolAddress((void**)&p_Wkvq, g_Wkvq);
    cudaGetSymbolAddress((void**)&p_bkvq, g_bkvq);
    cudaGetSymbolAddress((void**)&p_Wo,   g_Wo);
    cudaGetSymbolAddress((void**)&p_W1,   g_W1);
    cudaGetSymbolAddress((void**)&p_W2,   g_W2);

    cudaFuncSetAttribute(hgemm_kernel<1>, cudaFuncAttributeMaxDynamicSharedMemorySize, SMEM_BYTES);
    cudaFuncSetAttribute(hgemm_kernel<2>, cudaFuncAttributeMaxDynamicSharedMemorySize, SMEM_BYTES);
    cudaFuncSetAttribute(hgemm_kernel<3>, cudaFuncAttributeMaxDynamicSharedMemorySize, SMEM_BYTES);
    cudaFuncSetAttribute(hgemm_kernel<4>, cudaFuncAttributeMaxDynamicSharedMemorySize, SMEM_BYTES);
    cudaFuncSetAttribute(hgemm_kernel<5>, cudaFuncAttributeMaxDynamicSharedMemorySize, SMEM_BYTES);

    // 0. fused weight prep
    prep_kernel<<<3072, 256>>>(Wk, Wv, Wq, Wo, W1, W2, bk, bv, bq,
                               p_Wkvq, p_Wo, p_W1, p_W2, p_bkvq);

    // 1. exp_w (independent)
    expw_kernel<<<Tv, 256>>>(w, p_expw);

    // 2. LN1
    ln_kernel<<<BT, 128>>>(x, ln1_g, ln1_b, p_h);

    // 3. fused KVQ projection: [16384,512] @ [512,1536] -> half
    {
        dim3 grid(NKVQ / 128, BT / GM);
        hgemm_kernel<1><<<grid, 128, SMEM_BYTES>>>(p_h, p_Wkvq, p_bkvq, nullptr,
                                                   p_KVQ, BT, NKVQ, Dv);
    }

    // 4. fused kmax + build U (half KVQ, vectorized)
    buildU_kernel<<<TD / 4 / 256, 256>>>(p_KVQ, p_U);

    // 5. AFT core GEMM + fused gate: Y = sigmoid(Q) * num/den (half out)
    {
        dim3 grid(N2D / 128, Tv / GM);
        hgemm_kernel<5><<<grid, 128, SMEM_BYTES>>>(p_expw, p_U, nullptr, p_KVQ,
                                                   p_Y, Tv, N2D, Tv);
    }

    // 6. out = Y @ Wo + bo + x
    {
        dim3 grid(Dv / 128, BT / GM);
        hgemm_kernel<2><<<grid, 128, SMEM_BYTES>>>(p_Y, p_Wo, bo, x,
                                                   p_out, BT, Dv, Dv);
    }

    // 7. LN2
    ln_kernel<<<BT, 128>>>(p_out, ln2_g, ln2_b, p_h2);

    // 8. a1 = gelu(h2 @ W1 + b1) -> half
    {
        dim3 grid(Hv / 128, BT / GM);
        hgemm_kernel<3><<<grid, 128, SMEM_BYTES>>>(p_h2, p_W1, b1, nullptr,
                                                   p_a1, BT, Hv, Dv);
    }

    // 9. out = gelu(a1 @ W2 + b2) + out_residual
    {
        dim3 grid(Dv / 128, BT / GM);
        hgemm_kernel<4><<<grid, 128, SMEM_BYTES>>>(p_a1, p_W2, b2, p_out,
                                                   out, BT, Dv, Hv);
    }
}

// round 16
// speedup vs baseline: 1.0261x; 1.0077x over previous
#include <cuda_runtime.h>
#include <cuda_fp16.h>
#include <math.h>
#include <stdint.h>

// Problem constants
constexpr int Bv = 8;
constexpr int Tv = 2048;
constexpr int Dv = 512;
constexpr int Hv = 2048;
constexpr int BT = Bv * Tv;            // 16384
constexpr int TD = Tv * Dv;            // 1048576
constexpr int N2D = Bv * 2 * Dv;       // 8192
constexpr int NKVQ = 3 * Dv;           // 1536
constexpr int BTD = Bv * Tv * Dv;      // 8388608

// ---------------- scratch (device globals) ----------------
__device__ __half g_h   [BTD];                 // LN1 out
__device__ __half g_KVQ [(size_t)BT * NKVQ];   // K|V|Q fused, fp16
__device__ __half g_expw[(size_t)Tv * Tv];
__device__ __half g_U   [(size_t)Tv * N2D];    // interleaved (den,num) pairs
__device__ __half g_Y   [BTD];
__device__ float  g_out [BTD];
__device__ __half g_h2  [BTD];
__device__ __half g_a1  [(size_t)BT * Hv];
// half weight copies [K][N]
__device__ __half g_Wkvq[Dv * NKVQ];
__device__ float  g_bkvq[NKVQ];
__device__ __half g_Wo  [Dv * Dv];
__device__ __half g_W1  [Dv * Hv];
__device__ __half g_W2  [Hv * Dv];

// ---------------- LN helper: 2 rows per 256-thread block ----------------
__device__ __forceinline__ void ln_2rows(const float* __restrict__ x,
                                         const float* __restrict__ g,
                                         const float* __restrict__ b,
                                         __half* __restrict__ y,
                                         int rowpair, int tid) {
    const int half = tid >> 7;           // 0 or 1
    const int t = tid & 127;
    const int row = rowpair * 2 + half;
    const float4* xr = (const float4*)(x + (size_t)row * Dv);
    float4 v = xr[t];
    float s  = v.x + v.y + v.z + v.w;
    float sq = v.x * v.x + v.y * v.y + v.z * v.z + v.w * v.w;
    #pragma unroll
    for (int off = 16; off > 0; off >>= 1) {
        s  += __shfl_down_sync(0xffffffffu, s,  off);
        sq += __shfl_down_sync(0xffffffffu, sq, off);
    }
    __shared__ float ssum[2][4], ssq[2][4];
    __shared__ float smu[2], srstd[2];
    const int wid = t >> 5, lane = t & 31;
    if (lane == 0) { ssum[half][wid] = s; ssq[half][wid] = sq; }
    __syncthreads();
    if (t == 0) {
        float ts = ssum[half][0] + ssum[half][1] + ssum[half][2] + ssum[half][3];
        float tq = ssq[half][0] + ssq[half][1] + ssq[half][2] + ssq[half][3];
        float mu  = ts * (1.0f / Dv);
        float var = tq * (1.0f / Dv) - mu * mu;
        smu[half] = mu;
        srstd[half] = rsqrtf(var + 1e-5f);
    }
    __syncthreads();
    const float mu = smu[half], rstd = srstd[half];
    float4 gg = ((const float4*)g)[t];
    float4 bb = ((const float4*)b)[t];
    float o0 = (v.x - mu) * rstd * gg.x + bb.x;
    float o1 = (v.y - mu) * rstd * gg.y + bb.y;
    float o2 = (v.z - mu) * rstd * gg.z + bb.z;
    float o3 = (v.w - mu) * rstd * gg.w + bb.w;
    __half2* yr = (__half2*)(y + (size_t)row * Dv);
    yr[t * 2 + 0] = __floats2half2_rn(o0, o1);
    yr[t * 2 + 1] = __floats2half2_rn(o2, o3);
}

// ---------------- fused frontend: prep | exp_w | LN1 in one launch ---------
// blocks [0,3072): weight prep; [3072,5120): expw rows; [5120,13312): LN1 pairs
__global__ void frontend_kernel(const float* __restrict__ Wk,
                                const float* __restrict__ Wv,
                                const float* __restrict__ Wq,
                                const float* __restrict__ Wo,
                                const float* __restrict__ W1,
                                const float* __restrict__ W2,
                                const float* __restrict__ bk,
                                const float* __restrict__ bv,
                                const float* __restrict__ bq,
                                const float* __restrict__ w,
                                const float* __restrict__ x,
                                const float* __restrict__ ln1_g,
                                const float* __restrict__ ln1_b,
                                __half* __restrict__ dWkvq,
                                __half* __restrict__ dWo,
                                __half* __restrict__ dW1,
                                __half* __restrict__ dW2,
                                float* __restrict__ dbkvq,
                                __half* __restrict__ ew,
                                __half* __restrict__ h) {
    const int blk = blockIdx.x;
    const int tid = threadIdx.x;

    if (blk < 3072) {
        // ---- weight prep ----
        const int c = blk * 256 + tid;
        if (c < 1536)
            dbkvq[c] = (c < 512) ? bk[c] : (c < 1024) ? bv[c - 512] : bq[c - 1024];
        float4 v;
        __half* dst;
        int dc;
        if (c < 196608) {
            int d  = c / 384;
            int jj = c - d * 384;
            int seg = jj >> 7;
            int off = jj & 127;
            const float* W = (seg == 0) ? Wk : (seg == 1) ? Wv : Wq;
            v = ((const float4*)(W + (size_t)d * 512))[off];
            dst = dWkvq; dc = c;
        } else if (c < 262144) {
            dc = c - 196608;
            v = ((const float4*)Wo)[dc];
            dst = dWo;
        } else if (c < 524288) {
            dc = c - 262144;
            v = ((const float4*)W1)[dc];
            dst = dW1;
        } else {
            dc = c - 524288;
            v = ((const float4*)W2)[dc];
            dst = dW2;
        }
        ((__half2*)dst)[dc * 2 + 0] = __floats2half2_rn(v.x, v.y);
        ((__half2*)dst)[dc * 2 + 1] = __floats2half2_rn(v.z, v.w);
    } else if (blk < 5120) {
        // ---- exp_w row ----
        const int row = blk - 3072;
        const int t = tid;              // 0..255
        const float4* wr = (const float4*)(w + (size_t)row * Tv);
        float4 a = wr[t * 2], c4 = wr[t * 2 + 1];
        float m = fmaxf(fmaxf(fmaxf(a.x, a.y), fmaxf(a.z, a.w)),
                        fmaxf(fmaxf(c4.x, c4.y), fmaxf(c4.z, c4.w)));
        #pragma unroll
        for (int off = 16; off > 0; off >>= 1)
            m = fmaxf(m, __shfl_down_sync(0xffffffffu, m, off));
        __shared__ float sm8[8];
        __shared__ float s_max;
        const int wid = t >> 5, lane = t & 31;
        if (lane == 0) sm8[wid] = m;
        __syncthreads();
        if (t == 0) {
            float mm = sm8[0];
            #pragma unroll
            for (int i = 1; i < 8; i++) mm = fmaxf(mm, sm8[i]);
            s_max = mm;
        }
        __syncthreads();
        const float mx = s_max;
        __half2* er = (__half2*)(ew + (size_t)row * Tv);
        er[t * 4 + 0] = __floats2half2_rn(expf(a.x - mx), expf(a.y - mx));
        er[t * 4 + 1] = __floats2half2_rn(expf(a.z - mx), expf(a.w - mx));
        er[t * 4 + 2] = __floats2half2_rn(expf(c4.x - mx), expf(c4.y - mx));
        er[t * 4 + 3] = __floats2half2_rn(expf(c4.z - mx), expf(c4.w - mx));
    } else {
        // ---- LN1: two rows per block ----
        ln_2rows(x, ln1_g, ln1_b, h, blk - 5120, tid);
    }
}

// ---------------- LN2 standalone (2 rows per block) ----------------
__global__ void ln2_kernel(const float* __restrict__ x,
                           const float* __restrict__ g,
                           const float* __restrict__ b,
                           __half* __restrict__ y) {
    ln_2rows(x, g, b, y, blockIdx.x, threadIdx.x);
}

// ---------------- fused kmax + build U (half KVQ, 4 d per thread) ----------
__global__ void buildU_kernel(const __half* __restrict__ KVQ,
                              __half* __restrict__ U) {
    const int idx = blockIdx.x * blockDim.x + threadIdx.x;
    if (idx >= TD / 4) return;
    const int t  = idx >> 7;            // 128 d-groups per t
    const int d4 = (idx & 127) << 2;    // d base (multiple of 4)
    float4 kv[Bv];
    float4 m4 = make_float4(-1e30f, -1e30f, -1e30f, -1e30f);
    #pragma unroll
    for (int b = 0; b < Bv; b++) {
        uint2 raw = *(const uint2*)&KVQ[((size_t)(b * Tv + t)) * NKVQ + d4];
        float2 f01 = __half22float2(*(__half2*)&raw.x);
        float2 f23 = __half22float2(*(__half2*)&raw.y);
        kv[b] = make_float4(f01.x, f01.y, f23.x, f23.y);
        m4.x = fmaxf(m4.x, kv[b].x);
        m4.y = fmaxf(m4.y, kv[b].y);
        m4.z = fmaxf(m4.z, kv[b].z);
        m4.w = fmaxf(m4.w, kv[b].w);
    }
    __half2* Ubase = (__half2*)U + (size_t)t * (N2D / 2) + d4;
    #pragma unroll
    for (int b = 0; b < Bv; b++) {
        uint2 rawv = *(const uint2*)&KVQ[((size_t)(b * Tv + t)) * NKVQ + 512 + d4];
        float2 v01 = __half22float2(*(__half2*)&rawv.x);
        float2 v23 = __half22float2(*(__half2*)&rawv.y);
        float e0 = expf(kv[b].x - m4.x);
        float e1 = expf(kv[b].y - m4.y);
        float e2 = expf(kv[b].z - m4.z);
        float e3 = expf(kv[b].w - m4.w);
        __align__(16) __half2 hh[4];
        hh[0] = __floats2half2_rn(e0, e0 * v01.x);
        hh[1] = __floats2half2_rn(e1, e1 * v01.y);
        hh[2] = __floats2half2_rn(e2, e2 * v23.x);
        hh[3] = __floats2half2_rn(e3, e3 * v23.y);
        *(uint4*)(Ubase + b * 512) = *(uint4*)hh;
    }
}

// ============================================================================
// FP16 mma.sync GEMM (R13/R15-proven optimum): 64x128x64 CTA tile, 4 warps
// (32x64 warp tiles), 3-stage cp.async, fragment double-buffering, 3 CTAs/SM.
// ============================================================================
__device__ __forceinline__ float gelu_exact(float v) {
    return 0.5f * v * (1.0f + erff(v * 0.70710678118654752f));
}
__device__ __forceinline__ void cp_async16h(__half* dst, const __half* src) {
    uint32_t d = (uint32_t)__cvta_generic_to_shared(dst);
    asm volatile("cp.async.cg.shared.global [%0], [%1], 16;\n" :: "r"(d), "l"(src));
}
__device__ __forceinline__ void ldsm4(uint32_t* r, uint32_t addr) {
    asm volatile("ldmatrix.sync.aligned.m8n8.x4.shared.b16 {%0,%1,%2,%3}, [%4];"
        : "=r"(r[0]), "=r"(r[1]), "=r"(r[2]), "=r"(r[3]) : "r"(addr));
}
__device__ __forceinline__ void ldsm4t(uint32_t* r, uint32_t addr) {
    asm volatile("ldmatrix.sync.aligned.m8n8.x4.trans.shared.b16 {%0,%1,%2,%3}, [%4];"
        : "=r"(r[0]), "=r"(r[1]), "=r"(r[2]), "=r"(r[3]) : "r"(addr));
}
__device__ __forceinline__ void mma_f16(float* c, const uint32_t* a, const uint32_t* b) {
    asm volatile(
        "mma.sync.aligned.m16n8k16.row.col.f32.f16.f16.f32 "
        "{%0,%1,%2,%3}, {%4,%5,%6,%7}, {%8,%9}, {%0,%1,%2,%3};\n"
        : "+f"(c[0]), "+f"(c[1]), "+f"(c[2]), "+f"(c[3])
        : "r"(a[0]), "r"(a[1]), "r"(a[2]), "r"(a[3]), "r"(b[0]), "r"(b[1]));
}

constexpr int GM = 64;                         // CTA M tile
constexpr int BK = 64;
constexpr int A_HALVES = GM * BK;              // 4096 halves, 8KB
constexpr int B_HALVES = BK * 128;             // 8192 halves, 16KB
constexpr int STAGE_HALVES = A_HALVES + B_HALVES;     // 12288
constexpr int SMEM_BYTES = 3 * STAGE_HALVES * 2;      // 73728

// EPI: 1=+bias->half (KVQ), 2=+bias+res(f32)->f32, 3=gelu(+bias)->half,
//      4=gelu(+bias)+res(f32)->f32, 5=AFT gate (den,num)->sigmoid(Q)*num/den ->half
template <int EPI>
__global__ __launch_bounds__(128, 3)
void hgemm_kernel(const __half* __restrict__ A, const __half* __restrict__ B,
                  const float* __restrict__ bias, const void* __restrict__ res,
                  void* __restrict__ Cout, int M, int N, int K) {
    extern __shared__ __half sm[];
    const int tid  = threadIdx.x;
    const int lane = tid & 31;
    const int warp = tid >> 5;
    const int wrow = warp & 1;     // 2 x 32 rows
    const int wcol = warp >> 1;    // 2 x 64 cols
    const int bM = blockIdx.y * GM;
    const int bN = blockIdx.x * 128;
    const int lane15 = lane & 15;
    const int lanehi = lane >> 4;

    float c[2][8][4];
    #pragma unroll
    for (int i = 0; i < 2; i++)
        #pragma unroll
        for (int j = 0; j < 8; j++)
            #pragma unroll
            for (int k = 0; k < 4; k++) c[i][j][k] = 0.f;

    const int nk = K / BK;

    auto load_stage = [&](int kt, int s) {
        __half* As = sm + s * STAGE_HALVES;
        __half* Bs = As + A_HALVES;
        const __half* Ag = A + (size_t)bM * K + kt * BK;
        const __half* Bg = B + (size_t)(kt * BK) * N + bN;
        #pragma unroll
        for (int i = 0; i < 4; i++) {            // A: 512 16B chunks
            int ch = i * 128 + tid;
            int r = ch >> 3, cc = ch & 7;
            int pc = cc ^ (r & 7);
            cp_async16h(As + r * 64 + pc * 8, Ag + (size_t)r * K + cc * 8);
        }
        #pragma unroll
        for (int i = 0; i < 8; i++) {            // B: 1024 16B chunks
            int ch = i * 128 + tid;
            int k = ch >> 4, cc = ch & 15;
            int pc = cc ^ (k & 7);
            cp_async16h(Bs + k * 128 + pc * 8, Bg + (size_t)k * N + cc * 8);
        }
        asm volatile("cp.async.commit_group;\n");
    };

    load_stage(0, 0);
    load_stage(1, 1);

    int s_cur = 0;
    int s_next = 2;

    for (int kt = 0; kt < nk; kt++) {
        asm volatile("cp.async.wait_group 1;\n");
        __syncthreads();

        if (kt + 2 < nk) load_stage(kt + 2, s_next);
        else asm volatile("cp.async.commit_group;\n");

        const __half* As = sm + s_cur * STAGE_HALVES;
        uint32_t a_base = (uint32_t)__cvta_generic_to_shared(As);
        uint32_t b_base = a_base + A_HALVES * 2;
        if (++s_cur == 3) s_cur = 0;
        if (++s_next == 3) s_next = 0;

        uint32_t a[2][2][4], b[2][4][4];

        auto load_a = [&](int k16, uint32_t (*af)[4]) {
            #pragma unroll
            for (int mt = 0; mt < 2; mt++) {
                int r = wrow * 32 + mt * 16 + lane15;
                int cc = 2 * k16 + lanehi;
                int pc = cc ^ (r & 7);
                ldsm4(af[mt], a_base + (r * 64 + pc * 8) * 2);
            }
        };
        auto load_b = [&](int k16, uint32_t (*bf)[4]) {
            #pragma unroll
            for (int nt2 = 0; nt2 < 4; nt2++) {
                int kr = k16 * 16 + lane15;
                int cc = wcol * 8 + nt2 * 2 + lanehi;
                int pc = cc ^ (kr & 7);
                ldsm4t(bf[nt2], b_base + (kr * 128 + pc * 8) * 2);
            }
        };

        load_a(0, a[0]);
        load_b(0, b[0]);

        #pragma unroll
        for (int k16 = 0; k16 < 4; k16++) {
            const int cur = k16 & 1;
            if (k16 < 3) {
                load_a(k16 + 1, a[cur ^ 1]);
                load_b(k16 + 1, b[cur ^ 1]);
            }
            #pragma unroll
            for (int mt = 0; mt < 2; mt++)
                #pragma unroll
                for (int nt = 0; nt < 8; nt++)
                    mma_f16(c[mt][nt], a[cur][mt], &b[cur][nt >> 1][(nt & 1) * 2]);
        }
    }

    // epilogue
    #pragma unroll
    for (int mt = 0; mt < 2; mt++) {
        #pragma unroll
        for (int nt = 0; nt < 8; nt++) {
            const int row0 = bM + wrow * 32 + mt * 16 + (lane >> 2);
            const int col  = bN + wcol * 64 + nt * 8 + (lane & 3) * 2;
            #pragma unroll
            for (int h = 0; h < 2; h++) {
                const size_t row = row0 + h * 8;
                float v0 = c[mt][nt][h * 2 + 0];
                float v1 = c[mt][nt][h * 2 + 1];
                if (EPI == 5) {
                    int b  = col >> 10;
                    int d  = (col & 1023) >> 1;
                    size_t rb = (size_t)b * Tv + row;
                    float q = __half2float(
                        ((const __half*)res)[rb * NKVQ + 1024 + d]);  // res = KVQ
                    float sig = 1.0f / (1.0f + expf(-q));
                    ((__half*)Cout)[rb * 512 + d] = __float2half_rn(sig * v1 / v0);
                    continue;
                }
                if (EPI >= 1) { v0 += bias[col]; v1 += bias[col + 1]; }
                if (EPI == 3 || EPI == 4) { v0 = gelu_exact(v0); v1 = gelu_exact(v1); }
                if (EPI == 2 || EPI == 4) {
                    v0 += ((const float*)res)[row * N + col];
                    v1 += ((const float*)res)[row * N + col + 1];
                }
                if (EPI == 1 || EPI == 3) {
                    *(__half2*)((__half*)Cout + row * N + col) =
                        __floats2half2_rn(v0, v1);
                } else {
                    *(float2*)((float*)Cout + row * N + col) = make_float2(v0, v1);
                }
            }
        }
    }
}

// ---------------- launch ----------------
extern "C" void kernel_launch(void* const* d_in, const int* in_sizes, int n_in,
                              void* d_out, int out_size) {
    const float* x     = (const float*)d_in[0];
    const float* ln1_g = (const float*)d_in[1];
    const float* ln1_b = (const float*)d_in[2];
    const float* Wk    = (const float*)d_in[3];
    const float* bk    = (const float*)d_in[4];
    const float* Wv    = (const float*)d_in[5];
    const float* bv    = (const float*)d_in[6];
    const float* Wq    = (const float*)d_in[7];
    const float* bq    = (const float*)d_in[8];
    const float* w     = (const float*)d_in[9];
    const float* Wo    = (const float*)d_in[10];
    const float* bo    = (const float*)d_in[11];
    const float* ln2_g = (const float*)d_in[12];
    const float* ln2_b = (const float*)d_in[13];
    const float* W1    = (const float*)d_in[14];
    const float* b1    = (const float*)d_in[15];
    const float* W2    = (const float*)d_in[16];
    const float* b2    = (const float*)d_in[17];
    float* out = (float*)d_out;

    __half *p_h, *p_KVQ, *p_expw, *p_U, *p_Y, *p_h2, *p_a1, *p_Wkvq, *p_Wo,
           *p_W1, *p_W2;
    float *p_out, *p_bkvq;
    cudaGetSymbolAddress((void**)&p_h,    g_h);
    cudaGetSymbolAddress((void**)&p_KVQ,  g_KVQ);
    cudaGetSymbolAddress((void**)&p_expw, g_expw);
    cudaGetSymbolAddress((void**)&p_U,    g_U);
    cudaGetSymbolAddress((void**)&p_Y,    g_Y);
    cudaGetSymbolAddress((void**)&p_out,  g_out);
    cudaGetSymbolAddress((void**)&p_h2,   g_h2);
    cudaGetSymbolAddress((void**)&p_a1,   g_a1);
    cudaGetSymbolAddress((void**)&p_Wkvq, g_Wkvq);
    cudaGetSymbolAddress((void**)&p_bkvq, g_bkvq);
    cudaGetSymbolAddress((void**)&p_Wo,   g_Wo);
    cudaGetSymbolAddress((void**)&p_W1,   g_W1);
    cudaGetSymbolAddress((void**)&p_W2,   g_W2);

    cudaFuncSetAttribute(hgemm_kernel<1>, cudaFuncAttributeMaxDynamicSharedMemorySize, SMEM_BYTES);
    cudaFuncSetAttribute(hgemm_kernel<2>, cudaFuncAttributeMaxDynamicSharedMemorySize, SMEM_BYTES);
    cudaFuncSetAttribute(hgemm_kernel<3>, cudaFuncAttributeMaxDynamicSharedMemorySize, SMEM_BYTES);
    cudaFuncSetAttribute(hgemm_kernel<4>, cudaFuncAttributeMaxDynamicSharedMemorySize, SMEM_BYTES);
    cudaFuncSetAttribute(hgemm_kernel<5>, cudaFuncAttributeMaxDynamicSharedMemorySize, SMEM_BYTES);

    // 1. fused frontend: weight prep | exp_w | LN1 (single launch)
    frontend_kernel<<<13312, 256>>>(Wk, Wv, Wq, Wo, W1, W2, bk, bv, bq,
                                    w, x, ln1_g, ln1_b,
                                    p_Wkvq, p_Wo, p_W1, p_W2, p_bkvq,
                                    p_expw, p_h);

    // 2. fused KVQ projection: [16384,512] @ [512,1536] -> half
    {
        dim3 grid(NKVQ / 128, BT / GM);
        hgemm_kernel<1><<<grid, 128, SMEM_BYTES>>>(p_h, p_Wkvq, p_bkvq, nullptr,
                                                   p_KVQ, BT, NKVQ, Dv);
    }

    // 3. fused kmax + build U (half KVQ, vectorized)
    buildU_kernel<<<TD / 4 / 256, 256>>>(p_KVQ, p_U);

    // 4. AFT core GEMM + fused gate: Y = sigmoid(Q) * num/den (half out)
    {
        dim3 grid(N2D / 128, Tv / GM);
        hgemm_kernel<5><<<grid, 128, SMEM_BYTES>>>(p_expw, p_U, nullptr, p_KVQ,
                                                   p_Y, Tv, N2D, Tv);
    }

    // 5. out = Y @ Wo + bo + x
    {
        dim3 grid(Dv / 128, BT / GM);
        hgemm_kernel<2><<<grid, 128, SMEM_BYTES>>>(p_Y, p_Wo, bo, x,
                                                   p_out, BT, Dv, Dv);
    }

    // 6. LN2 (2 rows per block)
    ln2_kernel<<<BT / 2, 256>>>(p_out, ln2_g, ln2_b, p_h2);

    // 7. a1 = gelu(h2 @ W1 + b1) -> half
    {
        dim3 grid(Hv / 128, BT / GM);
        hgemm_kernel<3><<<grid, 128, SMEM_BYTES>>>(p_h2, p_W1, b1, nullptr,
                                                   p_a1, BT, Hv, Dv);
    }

    // 8. out = gelu(a1 @ W2 + b2) + out_residual
    {
        dim3 grid(Dv / 128, BT / GM);
        hgemm_kernel<4><<<grid, 128, SMEM_BYTES>>>(p_a1, p_W2, b2, p_out,
                                                   out, BT, Dv, Hv);
    }
}